// round 17
// baseline (speedup 1.0000x reference)
#include <cuda_runtime.h>
#include <cuda_fp16.h>
#include <cstdint>

#define NMAX 100000
#define EMAX 1600000
#define SCAN_CHUNK 512
#define CNT_EDGES_PER_BLOCK 2048

__device__ int    g_deg[NMAX + 1];
__device__ float  g_dinv[NMAX];
__device__ int    g_rowstart[NMAX];
__device__ int    g_cursor[NMAX];
__device__ int    g_src[EMAX];
__device__ __half g_h1s[NMAX * 64];
__device__ __half g_agg1[NMAX * 64];
__device__ __half g_h2s[NMAX * 32];

__device__ __forceinline__ void ldsm_a(uint32_t* r, uint32_t addr) {
    asm volatile("ldmatrix.sync.aligned.m8n8.x4.shared.b16 {%0,%1,%2,%3}, [%4];"
                 : "=r"(r[0]), "=r"(r[1]), "=r"(r[2]), "=r"(r[3]) : "r"(addr));
}

__device__ __forceinline__ void ldsm_bt(uint32_t* r, uint32_t addr) {
    asm volatile("ldmatrix.sync.aligned.m8n8.x4.trans.shared.b16 {%0,%1,%2,%3}, [%4];"
                 : "=r"(r[0]), "=r"(r[1]), "=r"(r[2]), "=r"(r[3]) : "r"(addr));
}

__device__ __forceinline__ void mma16816(float* d, const uint32_t* a, uint32_t b0, uint32_t b1) {
    asm volatile("mma.sync.aligned.m16n8k16.row.col.f32.f16.f16.f32 "
                 "{%0,%1,%2,%3}, {%4,%5,%6,%7}, {%8,%9}, {%0,%1,%2,%3};"
                 : "+f"(d[0]), "+f"(d[1]), "+f"(d[2]), "+f"(d[3])
                 : "r"(a[0]), "r"(a[1]), "r"(a[2]), "r"(a[3]), "r"(b0), "r"(b1));
}

__device__ __forceinline__ __half2 f2h(float lo, float hi) {
    return __floats2half2_rn(lo, hi);
}

// ---------------------------------------------------------------------------
// K1: blocks < gemmBlocks run tensor-core GEMM1 (h1raw = x@W1, fp16 out);
//     blocks >= gemmBlocks count in-degrees.
// ---------------------------------------------------------------------------
__global__ void __launch_bounds__(256) k_gemm1_count(const float* __restrict__ x,
                                                     const float* __restrict__ W,
                                                     const int* __restrict__ col,
                                                     int n, int e, int gemmBlocks) {
    if ((int)blockIdx.x >= gemmBlocks) {
        int b = blockIdx.x - gemmBlocks;
        int base = b * CNT_EDGES_PER_BLOCK + threadIdx.x;
#pragma unroll
        for (int j = 0; j < 8; j++) {
            int idx = base + j * 256;
            if (idx < e) atomicAdd(&g_deg[__ldg(&col[idx])], 1);
        }
        return;
    }

    __shared__ __align__(16) __half As[128][72];   // 144B stride
    __shared__ __align__(16) __half Bs[64][72];

    int t = threadIdx.x;
    int rowbase = blockIdx.x * 128;

    const float4* W4 = (const float4*)W;
    for (int i = t; i < 1024; i += 256) {
        int k = i >> 4;
        int c4 = i & 15;
        float4 v = W4[i];
        __half2 p0 = f2h(v.x, v.y);
        __half2 p1 = f2h(v.z, v.w);
        uint2 u;
        u.x = *(uint32_t*)&p0;
        u.y = *(uint32_t*)&p1;
        *(uint2*)&Bs[k][c4 * 4] = u;
    }

    const float4* x4 = (const float4*)x;
    for (int i = t; i < 2048; i += 256) {
        int r = i >> 4;
        int c4 = i & 15;
        int gr = rowbase + r;
        float4 v = make_float4(0.f, 0.f, 0.f, 0.f);
        if (gr < n) v = x4[gr * 16 + c4];
        __half2 p0 = f2h(v.x, v.y);
        __half2 p1 = f2h(v.z, v.w);
        uint2 u;
        u.x = *(uint32_t*)&p0;
        u.y = *(uint32_t*)&p1;
        *(uint2*)&As[r][c4 * 4] = u;
    }
    __syncthreads();

    int warp = t >> 5;
    int lane = t & 31;
    int m0 = warp * 16;

    float d[8][4];
#pragma unroll
    for (int nt = 0; nt < 8; nt++) {
        d[nt][0] = 0.f; d[nt][1] = 0.f; d[nt][2] = 0.f; d[nt][3] = 0.f;
    }

#pragma unroll
    for (int k0 = 0; k0 < 64; k0 += 16) {
        uint32_t afr[4];
        uint32_t aaddr = (uint32_t)__cvta_generic_to_shared(
            &As[m0 + (lane & 15)][k0 + (lane >> 4) * 8]);
        ldsm_a(afr, aaddr);
#pragma unroll
        for (int nn = 0; nn < 4; nn++) {
            uint32_t bfr[4];
            uint32_t baddr = (uint32_t)__cvta_generic_to_shared(
                &Bs[k0 + (lane & 15)][nn * 16 + (lane >> 4) * 8]);
            ldsm_bt(bfr, baddr);
            mma16816(d[nn * 2], afr, bfr[0], bfr[1]);
            mma16816(d[nn * 2 + 1], afr, bfr[2], bfr[3]);
        }
    }

    int r0 = rowbase + m0 + (lane >> 2);
    int cbase = (lane & 3) * 2;
#pragma unroll
    for (int nt = 0; nt < 8; nt++) {
        int colx = nt * 8 + cbase;
        __half2 h0 = f2h(d[nt][0], d[nt][1]);
        __half2 h1 = f2h(d[nt][2], d[nt][3]);
        if (r0 < n) *(__half2*)&g_h1s[r0 * 64 + colx] = h0;
        if (r0 + 8 < n) *(__half2*)&g_h1s[(r0 + 8) * 64 + colx] = h1;
    }
}

// ---------------------------------------------------------------------------
// Fused scan + dinv + in-place h1s dinv scaling.
// ---------------------------------------------------------------------------
__global__ void k_scan(int n) {
    __shared__ int s_warp[8];
    __shared__ int s_base;
    __shared__ float s_dinv[SCAN_CHUNK];
    int t = threadIdx.x;
    int base = blockIdx.x * SCAN_CHUNK;
    int i0 = base + 2 * t;
    int a = (i0 < n) ? g_deg[i0] : 0;
    int c = (i0 + 1 < n) ? g_deg[i0 + 1] : 0;
    float da = rsqrtf((float)(a + 1));
    float dc = rsqrtf((float)(c + 1));
    s_dinv[2 * t] = da;
    s_dinv[2 * t + 1] = dc;
    if (i0 < n) g_dinv[i0] = da;
    if (i0 + 1 < n) g_dinv[i0 + 1] = dc;

    int sum2 = a + c;
    int lane = t & 31;
    int wid = t >> 5;
    int v = sum2;
#pragma unroll
    for (int o = 1; o < 32; o <<= 1) {
        int u = __shfl_up_sync(0xFFFFFFFFu, v, o);
        if (lane >= o) v += u;
    }
    if (lane == 31) s_warp[wid] = v;
    __syncthreads();
    if (t < 8) {
        int w = s_warp[t];
#pragma unroll
        for (int o = 1; o < 8; o <<= 1) {
            int u = __shfl_up_sync(0xFFu, w, o);
            if (t >= o) w += u;
        }
        s_warp[t] = w;
    }
    __syncthreads();
    int woff = wid ? s_warp[wid - 1] : 0;
    int incl = v + woff;
    if (t == 255) s_base = atomicAdd(&g_deg[NMAX], incl);
    __syncthreads();
    int excl = incl - sum2 + s_base;
    if (i0 < n) { g_rowstart[i0] = excl; g_cursor[i0] = excl; }
    if (i0 + 1 < n) { g_rowstart[i0 + 1] = excl + a; g_cursor[i0 + 1] = excl + a; }

    for (int i = t; i < 4096; i += 256) {
        int rl = i >> 3;
        int c8 = i & 7;
        int node = base + rl;
        if (node >= n) break;
        float s = s_dinv[rl];
        uint4 raw = *(const uint4*)&g_h1s[node * 64 + c8 * 8];
        __half2* hp = (__half2*)&raw;
        __half2 o[4];
#pragma unroll
        for (int p = 0; p < 4; p++) {
            float2 f = __half22float2(hp[p]);
            o[p] = f2h(f.x * s, f.y * s);
        }
        *(uint4*)&g_h1s[node * 64 + c8 * 8] = *(uint4*)o;
    }
}

// ---------------------------------------------------------------------------
// CSR fill: 4 edges per thread, independent atomics/stores (MLP=4).
// ---------------------------------------------------------------------------
__global__ void k_fill(const int* __restrict__ row, const int* __restrict__ col, int e) {
    int base = blockIdx.x * 1024 + threadIdx.x;
    int idx[4];
    int pos[4];
    int rv[4];
#pragma unroll
    for (int j = 0; j < 4; j++) {
        int i = base + j * 256;
        idx[j] = i;
        if (i < e) {
            int c = col[i];
            pos[j] = atomicAdd(&g_cursor[c], 1);
            rv[j] = row[i];
        }
    }
#pragma unroll
    for (int j = 0; j < 4; j++) {
        if (idx[j] < e) g_src[pos[j]] = rv[j];
    }
}

// ---------------------------------------------------------------------------
// Aggregation layer 1: TWO warps per node (half0 = [0, deg/2) + self loop,
// half1 = [deg/2, deg)). Each warp runs the R11 x2-unroll gather on its half;
// halves combined via 128B smem staging + one __syncthreads.
// grp=lane>>3 (4 rows/step), sub=lane&7 (16B chunk).
// ---------------------------------------------------------------------------
__global__ void k_agg1(int n) {
    __shared__ __align__(16) __half s_part[8][64];   // 8 warps x 128B

    int warpInBlk = threadIdx.x >> 5;
    int gwarp = blockIdx.x * 8 + warpInBlk;
    int node = gwarp >> 1;
    int half = gwarp & 1;
    int lane = threadIdx.x & 31;
    bool active = (node < n);

    int grp = lane >> 3;
    int sub = lane & 7;

    __half2 acc[4];
    {
        __half2 z = f2h(0.f, 0.f);
        acc[0] = z; acc[1] = z; acc[2] = z; acc[3] = z;
    }

    if (active) {
        if (half == 0 && grp == 0) {
            uint4 raw = *(const uint4*)&g_h1s[node * 64 + sub * 8];
            __half2* hp = (__half2*)&raw;
            acc[0] = hp[0]; acc[1] = hp[1]; acc[2] = hp[2]; acc[3] = hp[3];
        }

        int deg = g_deg[node];
        int dh = deg >> 1;
        int start = g_rowstart[node] + (half ? dh : 0);
        int mycnt = half ? (deg - dh) : dh;

        for (int j0 = 0; j0 < mycnt; j0 += 32) {
            int cnt = min(32, mycnt - j0);
            int src = (lane < cnt) ? g_src[start + j0 + lane] : 0;
            int jj = 0;
            for (; jj + 8 <= cnt; jj += 8) {
                int sA = __shfl_sync(0xFFFFFFFFu, src, jj + grp);
                int sB = __shfl_sync(0xFFFFFFFFu, src, jj + 4 + grp);
                uint4 ra = *(const uint4*)&g_h1s[sA * 64 + sub * 8];
                uint4 rb = *(const uint4*)&g_h1s[sB * 64 + sub * 8];
                __half2* ha = (__half2*)&ra;
                __half2* hb = (__half2*)&rb;
                acc[0] = __hadd2(acc[0], ha[0]);
                acc[1] = __hadd2(acc[1], ha[1]);
                acc[2] = __hadd2(acc[2], ha[2]);
                acc[3] = __hadd2(acc[3], ha[3]);
                acc[0] = __hadd2(acc[0], hb[0]);
                acc[1] = __hadd2(acc[1], hb[1]);
                acc[2] = __hadd2(acc[2], hb[2]);
                acc[3] = __hadd2(acc[3], hb[3]);
            }
            for (; jj < cnt; jj += 4) {
                int sidx = jj + grp;
                int s = __shfl_sync(0xFFFFFFFFu, src, (sidx < cnt) ? sidx : 0);
                if (sidx < cnt) {
                    uint4 raw = *(const uint4*)&g_h1s[s * 64 + sub * 8];
                    __half2* hp = (__half2*)&raw;
                    acc[0] = __hadd2(acc[0], hp[0]);
                    acc[1] = __hadd2(acc[1], hp[1]);
                    acc[2] = __hadd2(acc[2], hp[2]);
                    acc[3] = __hadd2(acc[3], hp[3]);
                }
            }
        }

        // reduce the 4 lane-groups within this warp
#pragma unroll
        for (int o = 8; o <= 16; o <<= 1) {
#pragma unroll
            for (int p = 0; p < 4; p++) {
                unsigned u = __shfl_xor_sync(0xFFFFFFFFu, *(unsigned*)&acc[p], o);
                acc[p] = __hadd2(acc[p], *(__half2*)&u);
            }
        }
    }

    // stage this warp's partial row (128B)
    if (lane < 8) {
        *(uint4*)&s_part[warpInBlk][lane * 8] = *(uint4*)acc;
    }
    __syncthreads();

    // even warp combines with odd partner's partial and stores
    if (half == 0 && active && lane < 8) {
        uint4 other = *(const uint4*)&s_part[warpInBlk + 1][lane * 8];
        __half2* ho = (__half2*)&other;
        acc[0] = __hadd2(acc[0], ho[0]);
        acc[1] = __hadd2(acc[1], ho[1]);
        acc[2] = __hadd2(acc[2], ho[2]);
        acc[3] = __hadd2(acc[3], ho[3]);
        *(uint4*)&g_agg1[node * 64 + lane * 8] = *(uint4*)acc;
    }
}

// ---------------------------------------------------------------------------
// GEMM2 (tensor cores): a = relu(agg1*dinv + b1); h2s = fp16((a@W2)*dinv)
// 128-row tile, 8 warps x 16 rows, N=32 (2 B-tiles).
// ---------------------------------------------------------------------------
__global__ void __launch_bounds__(256) k_gemm2(const float* __restrict__ W2,
                                               const float* __restrict__ b1, int n) {
    __shared__ __align__(16) __half As[128][72];
    __shared__ __align__(16) __half Bs[64][72];

    int t = threadIdx.x;
    int rowbase = blockIdx.x * 128;

    const float4* W4 = (const float4*)W2;
    for (int i = t; i < 512; i += 256) {
        int k = i >> 3;
        int c4 = i & 7;
        float4 v = W4[i];
        __half2 p0 = f2h(v.x, v.y);
        __half2 p1 = f2h(v.z, v.w);
        uint2 u;
        u.x = *(uint32_t*)&p0;
        u.y = *(uint32_t*)&p1;
        *(uint2*)&Bs[k][c4 * 4] = u;
    }

    const uint2* a2 = (const uint2*)g_agg1;
    const float4* b14 = (const float4*)b1;
    for (int i = t; i < 2048; i += 256) {
        int r = i >> 4;
        int c4 = i & 15;
        int gr = rowbase + r;
        float4 v = make_float4(0.f, 0.f, 0.f, 0.f);
        if (gr < n) {
            uint2 raw = a2[gr * 16 + c4];
            float2 u01 = __half22float2(*(__half2*)&raw.x);
            float2 u23 = __half22float2(*(__half2*)&raw.y);
            float s = g_dinv[gr];
            float4 bb = b14[c4];
            v.x = fmaxf(fmaf(u01.x, s, bb.x), 0.f);
            v.y = fmaxf(fmaf(u01.y, s, bb.y), 0.f);
            v.z = fmaxf(fmaf(u23.x, s, bb.z), 0.f);
            v.w = fmaxf(fmaf(u23.y, s, bb.w), 0.f);
        }
        __half2 p0 = f2h(v.x, v.y);
        __half2 p1 = f2h(v.z, v.w);
        uint2 u;
        u.x = *(uint32_t*)&p0;
        u.y = *(uint32_t*)&p1;
        *(uint2*)&As[r][c4 * 4] = u;
    }
    __syncthreads();

    int warp = t >> 5;
    int lane = t & 31;
    int m0 = warp * 16;

    float d[4][4];
#pragma unroll
    for (int nt = 0; nt < 4; nt++) {
        d[nt][0] = 0.f; d[nt][1] = 0.f; d[nt][2] = 0.f; d[nt][3] = 0.f;
    }

#pragma unroll
    for (int k0 = 0; k0 < 64; k0 += 16) {
        uint32_t afr[4];
        uint32_t aaddr = (uint32_t)__cvta_generic_to_shared(
            &As[m0 + (lane & 15)][k0 + (lane >> 4) * 8]);
        ldsm_a(afr, aaddr);
#pragma unroll
        for (int nn = 0; nn < 2; nn++) {
            uint32_t bfr[4];
            uint32_t baddr = (uint32_t)__cvta_generic_to_shared(
                &Bs[k0 + (lane & 15)][nn * 16 + (lane >> 4) * 8]);
            ldsm_bt(bfr, baddr);
            mma16816(d[nn * 2], afr, bfr[0], bfr[1]);
            mma16816(d[nn * 2 + 1], afr, bfr[2], bfr[3]);
        }
    }

    int r0 = rowbase + m0 + (lane >> 2);
    int cbase = (lane & 3) * 2;
    float s0 = (r0 < n) ? g_dinv[r0] : 0.f;
    float s1 = (r0 + 8 < n) ? g_dinv[r0 + 8] : 0.f;
#pragma unroll
    for (int nt = 0; nt < 4; nt++) {
        int colx = nt * 8 + cbase;
        __half2 h0 = f2h(d[nt][0] * s0, d[nt][1] * s0);
        __half2 h1 = f2h(d[nt][2] * s1, d[nt][3] * s1);
        if (r0 < n) *(__half2*)&g_h2s[r0 * 32 + colx] = h0;
        if (r0 + 8 < n) *(__half2*)&g_h2s[(r0 + 8) * 32 + colx] = h1;
    }
}

// ---------------------------------------------------------------------------
// Aggregation layer 2 + log_softmax. 64B rows: grp=lane>>2 (8 rows/step),
// sub=lane&3. Unrolled x2 (16 sources in flight).
// ---------------------------------------------------------------------------
__global__ void k_agg2_lsm(const float* __restrict__ b2, float* __restrict__ out, int n) {
    __shared__ __align__(16) __half s_red[8][32];

    int warp = threadIdx.x >> 5;
    int gw = (blockIdx.x * blockDim.x + threadIdx.x) >> 5;
    int lane = threadIdx.x & 31;
    if (gw >= n) return;

    int grp = lane >> 2;
    int sub = lane & 3;

    __half2 acc[4];
    if (grp == 0) {
        uint4 raw = *(const uint4*)&g_h2s[gw * 32 + sub * 8];
        __half2* hp = (__half2*)&raw;
        acc[0] = hp[0]; acc[1] = hp[1]; acc[2] = hp[2]; acc[3] = hp[3];
    } else {
        __half2 z = f2h(0.f, 0.f);
        acc[0] = z; acc[1] = z; acc[2] = z; acc[3] = z;
    }

    int start = g_rowstart[gw];
    int deg = g_deg[gw];

    for (int j0 = 0; j0 < deg; j0 += 32) {
        int cnt = min(32, deg - j0);
        int src = (lane < cnt) ? g_src[start + j0 + lane] : 0;
        int jj = 0;
        for (; jj + 16 <= cnt; jj += 16) {
            int sA = __shfl_sync(0xFFFFFFFFu, src, jj + grp);
            int sB = __shfl_sync(0xFFFFFFFFu, src, jj + 8 + grp);
            uint4 ra = *(const uint4*)&g_h2s[sA * 32 + sub * 8];
            uint4 rb = *(const uint4*)&g_h2s[sB * 32 + sub * 8];
            __half2* ha = (__half2*)&ra;
            __half2* hb = (__half2*)&rb;
#pragma unroll
            for (int p = 0; p < 4; p++) {
                acc[p] = __hadd2(acc[p], ha[p]);
                acc[p] = __hadd2(acc[p], hb[p]);
            }
        }
        for (; jj < cnt; jj += 8) {
            int sidx = jj + grp;
            int s = __shfl_sync(0xFFFFFFFFu, src, (sidx < cnt) ? sidx : 0);
            if (sidx < cnt) {
                uint4 raw = *(const uint4*)&g_h2s[s * 32 + sub * 8];
                __half2* hp = (__half2*)&raw;
#pragma unroll
                for (int p = 0; p < 4; p++) {
                    acc[p] = __hadd2(acc[p], hp[p]);
                }
            }
        }
    }

#pragma unroll
    for (int o = 4; o <= 16; o <<= 1) {
#pragma unroll
        for (int p = 0; p < 4; p++) {
            unsigned u = __shfl_xor_sync(0xFFFFFFFFu, *(unsigned*)&acc[p], o);
            acc[p] = __hadd2(acc[p], *(__half2*)&u);
        }
    }

    if (lane < 4) {
        *(uint4*)&s_red[warp][lane * 8] = *(uint4*)acc;
    }
    __syncwarp();

    float z = fmaf(__half2float(s_red[warp][lane]), g_dinv[gw], b2[lane]);
    float m = z;
#pragma unroll
    for (int o = 16; o; o >>= 1) m = fmaxf(m, __shfl_xor_sync(0xFFFFFFFFu, m, o));
    float ex = expf(z - m);
    float s = ex;
#pragma unroll
    for (int o = 16; o; o >>= 1) s += __shfl_xor_sync(0xFFFFFFFFu, s, o);
    out[gw * 32 + lane] = z - m - logf(s);
}

// ---------------------------------------------------------------------------
extern "C" void kernel_launch(void* const* d_in, const int* in_sizes, int n_in,
                              void* d_out, int out_size) {
    const float* x = (const float*)d_in[0];
    const int* ei = (const int*)d_in[1];
    const float* W1 = (const float*)d_in[2];
    const float* b1 = (const float*)d_in[3];
    const float* W2 = (const float*)d_in[4];
    const float* b2 = (const float*)d_in[5];
    float* out = (float*)d_out;

    int n = in_sizes[0] / 64;
    int e = in_sizes[1] / 2;
    const int* row = ei;
    const int* col = ei + e;

    void* degp = 0;
    cudaGetSymbolAddress(&degp, g_deg);
    cudaMemsetAsync(degp, 0, (NMAX + 1) * sizeof(int));

    int gemmBlocks = (n + 127) / 128;
    int cntBlocks = (e + CNT_EDGES_PER_BLOCK - 1) / CNT_EDGES_PER_BLOCK;
    k_gemm1_count<<<gemmBlocks + cntBlocks, 256>>>(x, W1, col, n, e, gemmBlocks);

    int nb = (n + SCAN_CHUNK - 1) / SCAN_CHUNK;
    k_scan<<<nb, 256>>>(n);
    k_fill<<<(e + 1023) / 1024, 256>>>(row, col, e);

    // two warps per node: 2n warps, 8 warps per 256-thread block
    k_agg1<<<(2 * n + 7) / 8, 256>>>(n);

    k_gemm2<<<(n + 127) / 128, 256>>>(W2, b1, n);
    k_agg2_lsm<<<(n + 7) / 8, 256>>>(b2, out, n);
}